// round 15
// baseline (speedup 1.0000x reference)
#include <cuda_runtime.h>
#include <cuda_bf16.h>
#include <cuda_fp16.h>
#include <cstdint>

#define Bn 4
#define Ss 2048
#define Ee 1024
#define Hh 16
#define HD 64

// Pre-split fp16 inputs (filled by split_xw). X = Xh + Xl exactly (to 2^-22).
__device__ __align__(16) __half g_Xh[(size_t)Bn * Ss * Ee];
__device__ __align__(16) __half g_Xl[(size_t)Bn * Ss * Ee];
__device__ __align__(16) __half g_Wh[(size_t)3 * Ee * Ee];
__device__ __align__(16) __half g_Wl[(size_t)3 * Ee * Ee];

// fp16 attention operands (Q pre-scaled by 1/32). Q/K: [b,h,s,d]; V: [b,h,d,s].
__device__ __align__(16) __half g_Qh[(size_t)Bn * Hh * Ss * HD];
__device__ __align__(16) __half g_Kh[(size_t)Bn * Hh * Ss * HD];
__device__ __align__(16) __half g_Vth[(size_t)Bn * Hh * Ss * HD];

// ===========================================================================
// Helpers
// ===========================================================================
__device__ __forceinline__ uint32_t smem_u32(const void* p) {
    uint32_t a;
    asm("{ .reg .u64 t; cvta.to.shared.u64 t, %1; cvt.u32.u64 %0, t; }"
        : "=r"(a) : "l"(p));
    return a;
}

__device__ __forceinline__ void ldm_x4(uint32_t addr, uint32_t& r0, uint32_t& r1,
                                       uint32_t& r2, uint32_t& r3) {
    asm volatile("ldmatrix.sync.aligned.m8n8.x4.shared.b16 {%0,%1,%2,%3}, [%4];"
                 : "=r"(r0), "=r"(r1), "=r"(r2), "=r"(r3) : "r"(addr));
}

// fp16 MMA
__device__ __forceinline__ void mma16816h(float* d, const uint32_t* a,
                                          uint32_t b0, uint32_t b1) {
    asm volatile(
        "mma.sync.aligned.m16n8k16.row.col.f32.f16.f16.f32 "
        "{%0,%1,%2,%3}, {%4,%5,%6,%7}, {%8,%9}, {%0,%1,%2,%3};"
        : "+f"(d[0]), "+f"(d[1]), "+f"(d[2]), "+f"(d[3])
        : "r"(a[0]), "r"(a[1]), "r"(a[2]), "r"(a[3]), "r"(b0), "r"(b1));
}

__device__ __forceinline__ void cpa16(uint32_t dst, const void* src) {
    asm volatile("cp.async.cg.shared.global [%0], [%1], 16;"
                 :: "r"(dst), "l"(src) : "memory");
}
#define CP_COMMIT() asm volatile("cp.async.commit_group;" ::: "memory")
#define CP_WAIT0()  asm volatile("cp.async.wait_group 0;" ::: "memory")
#define CP_WAIT1()  asm volatile("cp.async.wait_group 1;" ::: "memory")

__device__ __forceinline__ float ex2f(float x) {
    float r;
    asm("ex2.approx.ftz.f32 %0, %1;" : "=f"(r) : "f"(x));
    return r;
}

// fp32 pair -> fp16x2 hi + fp16x2 lo (residual)
__device__ __forceinline__ void splitPh(float x, float y, uint32_t& hi, uint32_t& lo) {
    __half2 h = __floats2half2_rn(x, y);
    float2 f = __half22float2(h);
    __half2 l = __floats2half2_rn(x - f.x, y - f.y);
    hi = *reinterpret_cast<uint32_t*>(&h);
    lo = *reinterpret_cast<uint32_t*>(&l);
}

// ===========================================================================
// Pre-pass: split X and W into fp16 hi/lo (~18 us).
// ===========================================================================
__global__ void split_xw(const float* __restrict__ x, const float* __restrict__ wq,
                         const float* __restrict__ wk, const float* __restrict__ wv)
{
    const int XN2 = (Bn * Ss * Ee) / 2;
    const int WN2 = (Ee * Ee) / 2;
    const int total = XN2 + 3 * WN2;
    for (int i = blockIdx.x * blockDim.x + threadIdx.x; i < total;
         i += gridDim.x * blockDim.x) {
        float2 v;
        uint32_t hi, lo;
        if (i < XN2) {
            v = reinterpret_cast<const float2*>(x)[i];
            splitPh(v.x, v.y, hi, lo);
            reinterpret_cast<uint32_t*>(g_Xh)[i] = hi;
            reinterpret_cast<uint32_t*>(g_Xl)[i] = lo;
        } else {
            int r = i - XN2;
            int w = r / WN2;
            int j = r - w * WN2;
            const float* src = (w == 0) ? wq : (w == 1) ? wk : wv;
            v = reinterpret_cast<const float2*>(src)[j];
            splitPh(v.x, v.y, hi, lo);
            reinterpret_cast<uint32_t*>(g_Wh)[r] = hi;
            reinterpret_cast<uint32_t*>(g_Wl)[r] = lo;
        }
    }
}

// ===========================================================================
// Fused QKV projection (fp16). Q,K (z<2): 2-term (Xh.Wh + Xl.Wh; W eff. fp16).
// V (z==2): 3-term (+ Xh.Wl). cp.async double-buffered, tile 128x128, BK=64.
// ===========================================================================
#define SECB 18432
#define STGB (4 * SECB)
#define PROJ_SMEM (2 * STGB)
#define NCHP 16

__global__ __launch_bounds__(256, 1)
void proj_tc()
{
    extern __shared__ __align__(16) char sm[];
    const int t    = threadIdx.x;
    const int wid  = t >> 5;
    const int lane = t & 31;
    const int n0   = blockIdx.x * 128;
    const int m0   = blockIdx.y * 128;
    const int z    = blockIdx.z;
    const bool fullV = (z == 2);

    const __half* __restrict__ Wh = g_Wh + (size_t)z * Ee * Ee;
    const __half* __restrict__ Wl = g_Wl + (size_t)z * Ee * Ee;

    const int wm = (wid >> 1) * 32;
    const int wn = (wid & 1) * 64;
    const uint32_t smb = smem_u32(sm);

    const int lr = lane & 7;
    const uint32_t aRowOff = (uint32_t)((lr + ((lane >> 3) & 1) * 8) * 144
                                        + (lane >> 4) * 16);
    const uint32_t bRowOff = (uint32_t)((lr + ((lane >> 4) & 1) * 8) * 144
                                        + ((lane >> 3) & 1) * 16);

    float acc[2][8][4];
#pragma unroll
    for (int i = 0; i < 2; i++)
#pragma unroll
        for (int j = 0; j < 8; j++)
#pragma unroll
            for (int v = 0; v < 4; v++) acc[i][j][v] = 0.f;

    auto issue_chunk = [&](int c, int stg) {
        const int k0 = c * 64;
        const uint32_t base = smb + stg * STGB;
#pragma unroll
        for (int j = 0; j < 16; j++) {
            int gi  = t + j * 256;
            int sec = gi >> 10;
            int idx = gi & 1023;
            int row = idx >> 3;
            int c8  = idx & 7;
            if (sec == 3 && !fullV) continue;   // Wl unused for Q,K
            uint32_t dst = base + sec * SECB + row * 144 + c8 * 16;
            const __half* src;
            if (sec == 0)      src = g_Xh + (size_t)(m0 + row) * Ee + k0 + c8 * 8;
            else if (sec == 1) src = g_Xl + (size_t)(m0 + row) * Ee + k0 + c8 * 8;
            else if (sec == 2) src = Wh + (size_t)(n0 + row) * Ee + k0 + c8 * 8;
            else               src = Wl + (size_t)(n0 + row) * Ee + k0 + c8 * 8;
            cpa16(dst, src);
        }
        CP_COMMIT();
    };

    issue_chunk(0, 0);

    for (int c = 0; c < NCHP; ++c) {
        const int cur = c & 1;
        if (c + 1 < NCHP) { issue_chunk(c + 1, 1 - cur); CP_WAIT1(); }
        else              { CP_WAIT0(); }
        __syncthreads();

        const uint32_t sb = smb + cur * STGB;
#pragma unroll
        for (int kt = 0; kt < 4; kt++) {
            const uint32_t kb = kt * 32;
            uint32_t ah[2][4], al[2][4], bh[4][4], bl[4][4];
#pragma unroll
            for (int mt = 0; mt < 2; mt++) {
                uint32_t ro = sb + (uint32_t)((wm + mt * 16) * 144) + aRowOff + kb;
                ldm_x4(ro,        ah[mt][0], ah[mt][1], ah[mt][2], ah[mt][3]);
                ldm_x4(ro + SECB, al[mt][0], al[mt][1], al[mt][2], al[mt][3]);
            }
#pragma unroll
            for (int u = 0; u < 4; u++) {
                uint32_t ro = sb + 2 * SECB + (uint32_t)((wn + u * 16) * 144)
                              + bRowOff + kb;
                ldm_x4(ro, bh[u][0], bh[u][1], bh[u][2], bh[u][3]);
                if (fullV)
                    ldm_x4(ro + SECB, bl[u][0], bl[u][1], bl[u][2], bl[u][3]);
            }
#pragma unroll
            for (int mt = 0; mt < 2; mt++)
#pragma unroll
                for (int nt = 0; nt < 8; nt++) {
                    uint32_t b0h = bh[nt >> 1][(nt & 1) * 2];
                    uint32_t b1h = bh[nt >> 1][(nt & 1) * 2 + 1];
                    mma16816h(acc[mt][nt], ah[mt], b0h, b1h);
                    mma16816h(acc[mt][nt], al[mt], b0h, b1h);
                    if (fullV) {
                        uint32_t b0l = bl[nt >> 1][(nt & 1) * 2];
                        uint32_t b1l = bl[nt >> 1][(nt & 1) * 2 + 1];
                        mma16816h(acc[mt][nt], ah[mt], b0l, b1l);
                    }
                }
        }
        __syncthreads();
    }

    // Epilogue: Q,K -> single fp16 (Q scaled 1/32); V -> single fp16, transposed.
    const int g  = lane >> 2;
    const int tc = (lane & 3) * 2;
    const float scl = (z == 0) ? (1.0f / 32.0f) : 1.0f;
#pragma unroll
    for (int mt = 0; mt < 2; mt++) {
#pragma unroll
        for (int half = 0; half < 2; half++) {
            int m  = m0 + wm + mt * 16 + g + half * 8;
            int bb = m >> 11;
            int sq = m & 2047;
#pragma unroll
            for (int nt = 0; nt < 8; nt++) {
                int n  = n0 + wn + nt * 8 + tc;
                int hh = n >> 6;
                int dd = n & 63;
                float v0 = acc[mt][nt][half * 2] * scl;
                float v1 = acc[mt][nt][half * 2 + 1] * scl;
                if (z == 2) {
                    size_t vb = (size_t)(bb * Hh + hh) * HD * Ss;
                    g_Vth[vb + (size_t)dd * Ss + sq]       = __float2half_rn(v0);
                    g_Vth[vb + (size_t)(dd + 1) * Ss + sq] = __float2half_rn(v1);
                } else {
                    __half2 h = __floats2half2_rn(v0, v1);
                    size_t off = ((size_t)(bb * Hh + hh) * Ss + sq) * HD + dd;
                    __half* dst = (z == 0) ? g_Qh : g_Kh;
                    *reinterpret_cast<uint32_t*>(dst + off) =
                        *reinterpret_cast<uint32_t*>(&h);
                }
            }
        }
    }
}

// ===========================================================================
// fp16 flash attention. QK^T: 1 MMA; PV: 2-term (Ph.Vh + Pl.Vh).
// 128-thread CTAs (3/SM), 64 q-rows, 4 warps x 16 rows, warp-local softmax.
// KV buffers: 2 x (Kh|Vth), each section 64 rows x 144 B.
// ===========================================================================
#define ASEC 9216
#define ABUF (2 * ASEC)          // 18432
#define ATTN_SMEM (2 * ABUF)     // 36864
#define NKT (Ss / 64)            // 32

__global__ __launch_bounds__(128, 3)
void attn_tc(float* __restrict__ Out)
{
    extern __shared__ __align__(16) char sma[];
    const int t    = threadIdx.x;
    const int wid  = t >> 5;
    const int lane = t & 31;
    const int bh   = blockIdx.y;
    const int q0   = blockIdx.x * 64;

    const uint32_t smb = smem_u32(sma);
    const int lr = lane & 7;
    const uint32_t aOff = (uint32_t)((lr + ((lane >> 3) & 1) * 8) * 144
                                     + (lane >> 4) * 16);
    const uint32_t bOff = (uint32_t)((lr + ((lane >> 4) & 1) * 8) * 144
                                     + ((lane >> 3) & 1) * 16);

    // ---- Stage Q tile (64x64 fp16) into buf0 via cp.async ----
#pragma unroll
    for (int j = 0; j < 4; j++) {
        int gi  = t + j * 128;           // 0..511
        int row = gi >> 3;
        int c8  = gi & 7;
        const __half* src = g_Qh + (size_t)(bh * Ss + q0 + row) * HD + c8 * 8;
        cpa16(smb + row * 144 + c8 * 16, src);
    }
    CP_COMMIT();
    CP_WAIT0();
    __syncthreads();

    uint32_t qh[4][4];
#pragma unroll
    for (int kt2 = 0; kt2 < 4; kt2++) {
        uint32_t ad = smb + (uint32_t)(wid * 16 * 144) + aOff + kt2 * 32;
        ldm_x4(ad, qh[kt2][0], qh[kt2][1], qh[kt2][2], qh[kt2][3]);
    }
    __syncthreads();   // buf0 free for KV

    float o[8][4];
#pragma unroll
    for (int j = 0; j < 8; j++)
#pragma unroll
        for (int v = 0; v < 4; v++) o[j][v] = 0.f;
    float m0r = -1e30f, m1r = -1e30f, l0r = 0.f, l1r = 0.f;

    // Issue one KV tile: 2 sections x 64 rows x 8 x 16B = 8 cp.async/thread.
    auto issue_tile = [&](int kt, int buf) {
        const uint32_t base = smb + buf * ABUF;
#pragma unroll
        for (int j = 0; j < 8; j++) {
            int gi  = t + j * 128;       // 0..1023
            int sec = gi >> 9;           // 0..1
            int idx = gi & 511;
            int row = idx >> 3;
            int c8  = idx & 7;
            const __half* src;
            if (sec == 0) src = g_Kh  + (size_t)(bh * Ss + kt + row) * HD + c8 * 8;
            else          src = g_Vth + (size_t)(bh * HD + row) * Ss + kt + c8 * 8;
            cpa16(base + sec * ASEC + row * 144 + c8 * 16, src);
        }
        CP_COMMIT();
    };

    issue_tile(0, 0);

    const float L2E = 1.44269504f;

    for (int ti = 0; ti < NKT; ti++) {
        const int cur = ti & 1;
        if (ti + 1 < NKT) { issue_tile((ti + 1) * 64, 1 - cur); CP_WAIT1(); }
        else              { CP_WAIT0(); }
        __syncthreads();

        const uint32_t bb = smb + cur * ABUF;

        // ---- S = Q . K^T  (single fp16 MMA per atom) ----
        float s[8][4];
#pragma unroll
        for (int j = 0; j < 8; j++)
#pragma unroll
            for (int v = 0; v < 4; v++) s[j][v] = 0.f;

#pragma unroll
        for (int ks2 = 0; ks2 < 4; ks2++) {
            uint32_t kh[4][4];
#pragma unroll
            for (int u = 0; u < 4; u++) {
                uint32_t ad = bb + (uint32_t)(u * 16 * 144) + bOff + ks2 * 32;
                ldm_x4(ad, kh[u][0], kh[u][1], kh[u][2], kh[u][3]);
            }
#pragma unroll
            for (int j = 0; j < 8; j++) {
                int u = j >> 1, od = (j & 1) * 2;
                mma16816h(s[j], qh[ks2], kh[u][od], kh[u][od + 1]);
            }
        }

        // ---- Online softmax (warp-local; fused exp2) ----
        float rmx0 = -1e30f, rmx1 = -1e30f;
#pragma unroll
        for (int j = 0; j < 8; j++) {
            rmx0 = fmaxf(rmx0, fmaxf(s[j][0], s[j][1]));
            rmx1 = fmaxf(rmx1, fmaxf(s[j][2], s[j][3]));
        }
        rmx0 = fmaxf(rmx0, __shfl_xor_sync(0xffffffffu, rmx0, 1));
        rmx0 = fmaxf(rmx0, __shfl_xor_sync(0xffffffffu, rmx0, 2));
        rmx1 = fmaxf(rmx1, __shfl_xor_sync(0xffffffffu, rmx1, 1));
        rmx1 = fmaxf(rmx1, __shfl_xor_sync(0xffffffffu, rmx1, 2));

        float mn0 = fmaxf(m0r, rmx0), mn1 = fmaxf(m1r, rmx1);
        float a0 = ex2f((m0r - mn0) * L2E), a1 = ex2f((m1r - mn1) * L2E);
        m0r = mn0; m1r = mn1;
        const float nb0 = -mn0 * L2E, nb1 = -mn1 * L2E;

        float rs0 = 0.f, rs1 = 0.f;
#pragma unroll
        for (int j = 0; j < 8; j++) {
            s[j][0] = ex2f(fmaf(s[j][0], L2E, nb0));
            s[j][1] = ex2f(fmaf(s[j][1], L2E, nb0));
            s[j][2] = ex2f(fmaf(s[j][2], L2E, nb1));
            s[j][3] = ex2f(fmaf(s[j][3], L2E, nb1));
            rs0 += s[j][0] + s[j][1];
            rs1 += s[j][2] + s[j][3];
        }
        rs0 += __shfl_xor_sync(0xffffffffu, rs0, 1);
        rs0 += __shfl_xor_sync(0xffffffffu, rs0, 2);
        rs1 += __shfl_xor_sync(0xffffffffu, rs1, 1);
        rs1 += __shfl_xor_sync(0xffffffffu, rs1, 2);
        l0r = l0r * a0 + rs0;
        l1r = l1r * a1 + rs1;
#pragma unroll
        for (int j = 0; j < 8; j++) {
            o[j][0] *= a0; o[j][1] *= a0;
            o[j][2] *= a1; o[j][3] *= a1;
        }

        // ---- Pack P into fp16 A-fragments (hi + exact-residual lo) ----
        uint32_t ph[4][4], pl_[4][4];
#pragma unroll
        for (int ks2 = 0; ks2 < 4; ks2++) {
            int j0 = 2 * ks2, j1 = 2 * ks2 + 1;
            splitPh(s[j0][0], s[j0][1], ph[ks2][0], pl_[ks2][0]);
            splitPh(s[j0][2], s[j0][3], ph[ks2][1], pl_[ks2][1]);
            splitPh(s[j1][0], s[j1][1], ph[ks2][2], pl_[ks2][2]);
            splitPh(s[j1][2], s[j1][3], ph[ks2][3], pl_[ks2][3]);
        }

        // ---- O += P . V  (2-term fp16: Ph.Vh + Pl.Vh) ----
#pragma unroll
        for (int ks2 = 0; ks2 < 4; ks2++) {
            uint32_t vh[4][4];
#pragma unroll
            for (int u = 0; u < 4; u++) {
                uint32_t ad = bb + ASEC + (uint32_t)(u * 16 * 144) + bOff + ks2 * 32;
                ldm_x4(ad, vh[u][0], vh[u][1], vh[u][2], vh[u][3]);
            }
#pragma unroll
            for (int j = 0; j < 8; j++) {
                int u = j >> 1, od = (j & 1) * 2;
                mma16816h(o[j], ph[ks2], vh[u][od], vh[u][od + 1]);
                mma16816h(o[j], pl_[ks2], vh[u][od], vh[u][od + 1]);
            }
        }
        __syncthreads();   // next issue overwrites buf[1-cur]
    }

    // ---- Epilogue ----
    const int g  = lane >> 2;
    const int tc = (lane & 3) * 2;
    const int bb2 = bh >> 4;
    const int hh  = bh & 15;
    const float i0 = 1.0f / l0r, i1 = 1.0f / l1r;
    const int q  = q0 + wid * 16 + g;
#pragma unroll
    for (int j = 0; j < 8; j++) {
        int d = j * 8 + tc;
        size_t off0 = ((size_t)(bb2 * Ss + q)) * Ee + hh * 64 + d;
        size_t off1 = ((size_t)(bb2 * Ss + q + 8)) * Ee + hh * 64 + d;
        *(float2*)(Out + off0) = make_float2(o[j][0] * i0, o[j][1] * i0);
        *(float2*)(Out + off1) = make_float2(o[j][2] * i1, o[j][3] * i1);
    }
}

// ---------------------------------------------------------------------------
extern "C" void kernel_launch(void* const* d_in, const int* in_sizes, int n_in,
                              void* d_out, int out_size)
{
    const float* x  = (const float*)d_in[0];
    const float* Wq = (const float*)d_in[1];
    const float* Wk = (const float*)d_in[2];
    const float* Wv = (const float*)d_in[3];
    float* out = (float*)d_out;

    static bool attr_done = false;
    if (!attr_done) {
        cudaFuncSetAttribute(proj_tc, cudaFuncAttributeMaxDynamicSharedMemorySize,
                             PROJ_SMEM);
        cudaFuncSetAttribute(attn_tc, cudaFuncAttributeMaxDynamicSharedMemorySize,
                             ATTN_SMEM);
        attr_done = true;
    }

    split_xw<<<2048, 256>>>(x, Wq, Wk, Wv);

    dim3 pgrid(Ee / 128, (Bn * Ss) / 128, 3);   // (8, 64, 3)
    proj_tc<<<pgrid, 256, PROJ_SMEM>>>();

    dim3 agrid(Ss / 64, Bn * Hh);               // (32, 64)
    attn_tc<<<agrid, 128, ATTN_SMEM>>>(out);
}

// round 16
// speedup vs baseline: 1.5171x; 1.5171x over previous
#include <cuda_runtime.h>
#include <cuda_bf16.h>
#include <cuda_fp16.h>
#include <cstdint>

#define Bn 4
#define Ss 2048
#define Ee 1024
#define Hh 16
#define HD 64

// Pre-split fp16 inputs (filled by split_xw). X = Xh + Xl (exact to 2^-22).
__device__ __align__(16) __half g_Xh[(size_t)Bn * Ss * Ee];
__device__ __align__(16) __half g_Xl[(size_t)Bn * Ss * Ee];
__device__ __align__(16) __half g_Wh[(size_t)3 * Ee * Ee];
__device__ __align__(16) __half g_Wl[(size_t)3 * Ee * Ee];

// fp16 attention operands (Q pre-scaled by 1/32). Q/K: [b,h,s,d]; V: [b,h,d,s].
__device__ __align__(16) __half g_Qh[(size_t)Bn * Hh * Ss * HD];
__device__ __align__(16) __half g_Kh[(size_t)Bn * Hh * Ss * HD];
__device__ __align__(16) __half g_Vth[(size_t)Bn * Hh * Ss * HD];

// ===========================================================================
// Helpers
// ===========================================================================
__device__ __forceinline__ uint32_t smem_u32(const void* p) {
    uint32_t a;
    asm("{ .reg .u64 t; cvta.to.shared.u64 t, %1; cvt.u32.u64 %0, t; }"
        : "=r"(a) : "l"(p));
    return a;
}

__device__ __forceinline__ void ldm_x4(uint32_t addr, uint32_t& r0, uint32_t& r1,
                                       uint32_t& r2, uint32_t& r3) {
    asm volatile("ldmatrix.sync.aligned.m8n8.x4.shared.b16 {%0,%1,%2,%3}, [%4];"
                 : "=r"(r0), "=r"(r1), "=r"(r2), "=r"(r3) : "r"(addr));
}

// fp16 MMA
__device__ __forceinline__ void mma16816h(float* d, const uint32_t* a,
                                          uint32_t b0, uint32_t b1) {
    asm volatile(
        "mma.sync.aligned.m16n8k16.row.col.f32.f16.f16.f32 "
        "{%0,%1,%2,%3}, {%4,%5,%6,%7}, {%8,%9}, {%0,%1,%2,%3};"
        : "+f"(d[0]), "+f"(d[1]), "+f"(d[2]), "+f"(d[3])
        : "r"(a[0]), "r"(a[1]), "r"(a[2]), "r"(a[3]), "r"(b0), "r"(b1));
}

__device__ __forceinline__ void cpa16(uint32_t dst, const void* src) {
    asm volatile("cp.async.cg.shared.global [%0], [%1], 16;"
                 :: "r"(dst), "l"(src) : "memory");
}
#define CP_COMMIT() asm volatile("cp.async.commit_group;" ::: "memory")
#define CP_WAIT0()  asm volatile("cp.async.wait_group 0;" ::: "memory")
#define CP_WAIT1()  asm volatile("cp.async.wait_group 1;" ::: "memory")
#define CP_WAIT2()  asm volatile("cp.async.wait_group 2;" ::: "memory")

__device__ __forceinline__ float ex2f(float x) {
    float r;
    asm("ex2.approx.ftz.f32 %0, %1;" : "=f"(r) : "f"(x));
    return r;
}

// fp32 pair -> fp16x2 hi + fp16x2 lo (residual)
__device__ __forceinline__ void splitPh(float x, float y, uint32_t& hi, uint32_t& lo) {
    __half2 h = __floats2half2_rn(x, y);
    float2 f = __half22float2(h);
    __half2 l = __floats2half2_rn(x - f.x, y - f.y);
    hi = *reinterpret_cast<uint32_t*>(&h);
    lo = *reinterpret_cast<uint32_t*>(&l);
}

// ===========================================================================
// Pre-pass: split X and W into fp16 hi/lo (~22 us).
// ===========================================================================
__global__ void split_xw(const float* __restrict__ x, const float* __restrict__ wq,
                         const float* __restrict__ wk, const float* __restrict__ wv)
{
    const int XN2 = (Bn * Ss * Ee) / 2;
    const int WN2 = (Ee * Ee) / 2;
    const int total = XN2 + 3 * WN2;
    for (int i = blockIdx.x * blockDim.x + threadIdx.x; i < total;
         i += gridDim.x * blockDim.x) {
        float2 v;
        uint32_t hi, lo;
        if (i < XN2) {
            v = reinterpret_cast<const float2*>(x)[i];
            splitPh(v.x, v.y, hi, lo);
            reinterpret_cast<uint32_t*>(g_Xh)[i] = hi;
            reinterpret_cast<uint32_t*>(g_Xl)[i] = lo;
        } else {
            int r = i - XN2;
            int w = r / WN2;
            int j = r - w * WN2;
            const float* src = (w == 0) ? wq : (w == 1) ? wk : wv;
            v = reinterpret_cast<const float2*>(src)[j];
            splitPh(v.x, v.y, hi, lo);
            reinterpret_cast<uint32_t*>(g_Wh)[r] = hi;
            reinterpret_cast<uint32_t*>(g_Wl)[r] = lo;
        }
    }
}

// ===========================================================================
// Fused QKV projection (fp16). Q,K (z<2): 2-term (Xh.Wh + Xl.Wh).
// V (z==2): 3-term (+ Xh.Wl). cp.async double-buffered, tile 128x128, BK=64.
// ===========================================================================
#define SECB 18432
#define STGB (4 * SECB)
#define PROJ_SMEM (2 * STGB)
#define NCHP 16

__global__ __launch_bounds__(256, 1)
void proj_tc()
{
    extern __shared__ __align__(16) char sm[];
    const int t    = threadIdx.x;
    const int wid  = t >> 5;
    const int lane = t & 31;
    const int n0   = blockIdx.x * 128;
    const int m0   = blockIdx.y * 128;
    const int z    = blockIdx.z;
    const bool fullV = (z == 2);

    const __half* __restrict__ Wh = g_Wh + (size_t)z * Ee * Ee;
    const __half* __restrict__ Wl = g_Wl + (size_t)z * Ee * Ee;

    const int wm = (wid >> 1) * 32;
    const int wn = (wid & 1) * 64;
    const uint32_t smb = smem_u32(sm);

    const int lr = lane & 7;
    const uint32_t aRowOff = (uint32_t)((lr + ((lane >> 3) & 1) * 8) * 144
                                        + (lane >> 4) * 16);
    const uint32_t bRowOff = (uint32_t)((lr + ((lane >> 4) & 1) * 8) * 144
                                        + ((lane >> 3) & 1) * 16);

    float acc[2][8][4];
#pragma unroll
    for (int i = 0; i < 2; i++)
#pragma unroll
        for (int j = 0; j < 8; j++)
#pragma unroll
            for (int v = 0; v < 4; v++) acc[i][j][v] = 0.f;

    auto issue_chunk = [&](int c, int stg) {
        const int k0 = c * 64;
        const uint32_t base = smb + stg * STGB;
#pragma unroll
        for (int j = 0; j < 16; j++) {
            int gi  = t + j * 256;
            int sec = gi >> 10;
            int idx = gi & 1023;
            int row = idx >> 3;
            int c8  = idx & 7;
            if (sec == 3 && !fullV) continue;   // Wl unused for Q,K
            uint32_t dst = base + sec * SECB + row * 144 + c8 * 16;
            const __half* src;
            if (sec == 0)      src = g_Xh + (size_t)(m0 + row) * Ee + k0 + c8 * 8;
            else if (sec == 1) src = g_Xl + (size_t)(m0 + row) * Ee + k0 + c8 * 8;
            else if (sec == 2) src = Wh + (size_t)(n0 + row) * Ee + k0 + c8 * 8;
            else               src = Wl + (size_t)(n0 + row) * Ee + k0 + c8 * 8;
            cpa16(dst, src);
        }
        CP_COMMIT();
    };

    issue_chunk(0, 0);

    for (int c = 0; c < NCHP; ++c) {
        const int cur = c & 1;
        if (c + 1 < NCHP) { issue_chunk(c + 1, 1 - cur); CP_WAIT1(); }
        else              { CP_WAIT0(); }
        __syncthreads();

        const uint32_t sb = smb + cur * STGB;
#pragma unroll
        for (int kt = 0; kt < 4; kt++) {
            const uint32_t kb = kt * 32;
            uint32_t ah[2][4], al[2][4], bh[4][4], bl[4][4];
#pragma unroll
            for (int mt = 0; mt < 2; mt++) {
                uint32_t ro = sb + (uint32_t)((wm + mt * 16) * 144) + aRowOff + kb;
                ldm_x4(ro,        ah[mt][0], ah[mt][1], ah[mt][2], ah[mt][3]);
                ldm_x4(ro + SECB, al[mt][0], al[mt][1], al[mt][2], al[mt][3]);
            }
#pragma unroll
            for (int u = 0; u < 4; u++) {
                uint32_t ro = sb + 2 * SECB + (uint32_t)((wn + u * 16) * 144)
                              + bRowOff + kb;
                ldm_x4(ro, bh[u][0], bh[u][1], bh[u][2], bh[u][3]);
                if (fullV)
                    ldm_x4(ro + SECB, bl[u][0], bl[u][1], bl[u][2], bl[u][3]);
            }
#pragma unroll
            for (int mt = 0; mt < 2; mt++)
#pragma unroll
                for (int nt = 0; nt < 8; nt++) {
                    uint32_t b0h = bh[nt >> 1][(nt & 1) * 2];
                    uint32_t b1h = bh[nt >> 1][(nt & 1) * 2 + 1];
                    mma16816h(acc[mt][nt], ah[mt], b0h, b1h);
                    mma16816h(acc[mt][nt], al[mt], b0h, b1h);
                    if (fullV) {
                        uint32_t b0l = bl[nt >> 1][(nt & 1) * 2];
                        uint32_t b1l = bl[nt >> 1][(nt & 1) * 2 + 1];
                        mma16816h(acc[mt][nt], ah[mt], b0l, b1l);
                    }
                }
        }
        __syncthreads();
    }

    // Epilogue: Q,K -> single fp16 (Q scaled 1/32); V -> single fp16, transposed.
    const int g  = lane >> 2;
    const int tc = (lane & 3) * 2;
    const float scl = (z == 0) ? (1.0f / 32.0f) : 1.0f;
#pragma unroll
    for (int mt = 0; mt < 2; mt++) {
#pragma unroll
        for (int half = 0; half < 2; half++) {
            int m  = m0 + wm + mt * 16 + g + half * 8;
            int bb = m >> 11;
            int sq = m & 2047;
#pragma unroll
            for (int nt = 0; nt < 8; nt++) {
                int n  = n0 + wn + nt * 8 + tc;
                int hh = n >> 6;
                int dd = n & 63;
                float v0 = acc[mt][nt][half * 2] * scl;
                float v1 = acc[mt][nt][half * 2 + 1] * scl;
                if (z == 2) {
                    size_t vb = (size_t)(bb * Hh + hh) * HD * Ss;
                    g_Vth[vb + (size_t)dd * Ss + sq]       = __float2half_rn(v0);
                    g_Vth[vb + (size_t)(dd + 1) * Ss + sq] = __float2half_rn(v1);
                } else {
                    __half2 h = __floats2half2_rn(v0, v1);
                    size_t off = ((size_t)(bb * Hh + hh) * Ss + sq) * HD + dd;
                    __half* dst = (z == 0) ? g_Qh : g_Kh;
                    *reinterpret_cast<uint32_t*>(dst + off) =
                        *reinterpret_cast<uint32_t*>(&h);
                }
            }
        }
    }
}

// ===========================================================================
// fp16 flash attention. QK^T: 1 MMA; PV: 2-term (Ph.Vh + Pl.Vh).
// 128-thread CTAs, 64 q-rows, 4 warps x 16 rows, warp-local softmax.
// THREE-stage cp.async pipeline, 3 x (Kh|Vth) buffers = 55296 B total —
// same smem footprint as the 832us R13 kernel (pins occupancy at 3-4 CTAs/SM,
// avoiding the 6-CTA L1tex-queue contention that regressed R14).
// ===========================================================================
#define ASEC 9216
#define ABUF (2 * ASEC)          // 18432 per stage
#define NSTG 3
#define ATTN_SMEM (NSTG * ABUF)  // 55296
#define NKT (Ss / 64)            // 32

__global__ __launch_bounds__(128, 3)
void attn_tc(float* __restrict__ Out)
{
    extern __shared__ __align__(16) char sma[];
    const int t    = threadIdx.x;
    const int wid  = t >> 5;
    const int lane = t & 31;
    const int bh   = blockIdx.y;
    const int q0   = blockIdx.x * 64;

    const uint32_t smb = smem_u32(sma);
    const int lr = lane & 7;
    const uint32_t aOff = (uint32_t)((lr + ((lane >> 3) & 1) * 8) * 144
                                     + (lane >> 4) * 16);
    const uint32_t bOff = (uint32_t)((lr + ((lane >> 4) & 1) * 8) * 144
                                     + ((lane >> 3) & 1) * 16);

    // ---- Stage Q tile (64x64 fp16) into stage0 via cp.async ----
#pragma unroll
    for (int j = 0; j < 4; j++) {
        int gi  = t + j * 128;           // 0..511
        int row = gi >> 3;
        int c8  = gi & 7;
        const __half* src = g_Qh + (size_t)(bh * Ss + q0 + row) * HD + c8 * 8;
        cpa16(smb + row * 144 + c8 * 16, src);
    }
    CP_COMMIT();
    CP_WAIT0();
    __syncthreads();

    uint32_t qh[4][4];
#pragma unroll
    for (int kt2 = 0; kt2 < 4; kt2++) {
        uint32_t ad = smb + (uint32_t)(wid * 16 * 144) + aOff + kt2 * 32;
        ldm_x4(ad, qh[kt2][0], qh[kt2][1], qh[kt2][2], qh[kt2][3]);
    }
    __syncthreads();   // stage0 free for KV

    float o[8][4];
#pragma unroll
    for (int j = 0; j < 8; j++)
#pragma unroll
        for (int v = 0; v < 4; v++) o[j][v] = 0.f;
    float m0r = -1e30f, m1r = -1e30f, l0r = 0.f, l1r = 0.f;

    // Issue one KV tile: 2 sections x 64 rows x 8 x 16B = 8 cp.async/thread.
    auto issue_tile = [&](int ti, int stg) {
        const int kt = ti * 64;
        const uint32_t base = smb + stg * ABUF;
#pragma unroll
        for (int j = 0; j < 8; j++) {
            int gi  = t + j * 128;       // 0..1023
            int sec = gi >> 9;           // 0..1
            int idx = gi & 511;
            int row = idx >> 3;
            int c8  = idx & 7;
            const __half* src;
            if (sec == 0) src = g_Kh  + (size_t)(bh * Ss + kt + row) * HD + c8 * 8;
            else          src = g_Vth + (size_t)(bh * HD + row) * Ss + kt + c8 * 8;
            cpa16(base + sec * ASEC + row * 144 + c8 * 16, src);
        }
        CP_COMMIT();
    };

    // Prologue: fill two stages.
    issue_tile(0, 0);
    issue_tile(1, 1);

    const float L2E = 1.44269504f;

    for (int ti = 0; ti < NKT; ti++) {
        const int cur = ti % NSTG;
        // Issue tile ti+2 into stage (ti+2)%3 == stage of tile ti-1 (done).
        if (ti + 2 < NKT) { issue_tile(ti + 2, (ti + 2) % NSTG); CP_WAIT2(); }
        else if (ti + 1 < NKT) { CP_WAIT1(); }
        else { CP_WAIT0(); }
        __syncthreads();

        const uint32_t bb = smb + cur * ABUF;

        // ---- S = Q . K^T  (single fp16 MMA per atom) ----
        float s[8][4];
#pragma unroll
        for (int j = 0; j < 8; j++)
#pragma unroll
            for (int v = 0; v < 4; v++) s[j][v] = 0.f;

#pragma unroll
        for (int ks2 = 0; ks2 < 4; ks2++) {
            uint32_t kh[4][4];
#pragma unroll
            for (int u = 0; u < 4; u++) {
                uint32_t ad = bb + (uint32_t)(u * 16 * 144) + bOff + ks2 * 32;
                ldm_x4(ad, kh[u][0], kh[u][1], kh[u][2], kh[u][3]);
            }
#pragma unroll
            for (int j = 0; j < 8; j++) {
                int u = j >> 1, od = (j & 1) * 2;
                mma16816h(s[j], qh[ks2], kh[u][od], kh[u][od + 1]);
            }
        }

        // ---- Online softmax (warp-local; fused exp2) ----
        float rmx0 = -1e30f, rmx1 = -1e30f;
#pragma unroll
        for (int j = 0; j < 8; j++) {
            rmx0 = fmaxf(rmx0, fmaxf(s[j][0], s[j][1]));
            rmx1 = fmaxf(rmx1, fmaxf(s[j][2], s[j][3]));
        }
        rmx0 = fmaxf(rmx0, __shfl_xor_sync(0xffffffffu, rmx0, 1));
        rmx0 = fmaxf(rmx0, __shfl_xor_sync(0xffffffffu, rmx0, 2));
        rmx1 = fmaxf(rmx1, __shfl_xor_sync(0xffffffffu, rmx1, 1));
        rmx1 = fmaxf(rmx1, __shfl_xor_sync(0xffffffffu, rmx1, 2));

        float mn0 = fmaxf(m0r, rmx0), mn1 = fmaxf(m1r, rmx1);
        float a0 = ex2f((m0r - mn0) * L2E), a1 = ex2f((m1r - mn1) * L2E);
        m0r = mn0; m1r = mn1;
        const float nb0 = -mn0 * L2E, nb1 = -mn1 * L2E;

        float rs0 = 0.f, rs1 = 0.f;
#pragma unroll
        for (int j = 0; j < 8; j++) {
            s[j][0] = ex2f(fmaf(s[j][0], L2E, nb0));
            s[j][1] = ex2f(fmaf(s[j][1], L2E, nb0));
            s[j][2] = ex2f(fmaf(s[j][2], L2E, nb1));
            s[j][3] = ex2f(fmaf(s[j][3], L2E, nb1));
            rs0 += s[j][0] + s[j][1];
            rs1 += s[j][2] + s[j][3];
        }
        rs0 += __shfl_xor_sync(0xffffffffu, rs0, 1);
        rs0 += __shfl_xor_sync(0xffffffffu, rs0, 2);
        rs1 += __shfl_xor_sync(0xffffffffu, rs1, 1);
        rs1 += __shfl_xor_sync(0xffffffffu, rs1, 2);
        l0r = l0r * a0 + rs0;
        l1r = l1r * a1 + rs1;
#pragma unroll
        for (int j = 0; j < 8; j++) {
            o[j][0] *= a0; o[j][1] *= a0;
            o[j][2] *= a1; o[j][3] *= a1;
        }

        // ---- Pack P into fp16 A-fragments (hi + exact-residual lo) ----
        uint32_t ph[4][4], pl_[4][4];
#pragma unroll
        for (int ks2 = 0; ks2 < 4; ks2++) {
            int j0 = 2 * ks2, j1 = 2 * ks2 + 1;
            splitPh(s[j0][0], s[j0][1], ph[ks2][0], pl_[ks2][0]);
            splitPh(s[j0][2], s[j0][3], ph[ks2][1], pl_[ks2][1]);
            splitPh(s[j1][0], s[j1][1], ph[ks2][2], pl_[ks2][2]);
            splitPh(s[j1][2], s[j1][3], ph[ks2][3], pl_[ks2][3]);
        }

        // ---- O += P . V  (2-term fp16: Ph.Vh + Pl.Vh) ----
#pragma unroll
        for (int ks2 = 0; ks2 < 4; ks2++) {
            uint32_t vh[4][4];
#pragma unroll
            for (int u = 0; u < 4; u++) {
                uint32_t ad = bb + ASEC + (uint32_t)(u * 16 * 144) + bOff + ks2 * 32;
                ldm_x4(ad, vh[u][0], vh[u][1], vh[u][2], vh[u][3]);
            }
#pragma unroll
            for (int j = 0; j < 8; j++) {
                int u = j >> 1, od = (j & 1) * 2;
                mma16816h(o[j], ph[ks2], vh[u][od], vh[u][od + 1]);
                mma16816h(o[j], pl_[ks2], vh[u][od], vh[u][od + 1]);
            }
        }
        __syncthreads();   // frees stage cur for the issue at iter ti+1
    }

    // ---- Epilogue ----
    const int g  = lane >> 2;
    const int tc = (lane & 3) * 2;
    const int bb2 = bh >> 4;
    const int hh  = bh & 15;
    const float i0 = 1.0f / l0r, i1 = 1.0f / l1r;
    const int q  = q0 + wid * 16 + g;
#pragma unroll
    for (int j = 0; j < 8; j++) {
        int d = j * 8 + tc;
        size_t off0 = ((size_t)(bb2 * Ss + q)) * Ee + hh * 64 + d;
        size_t off1 = ((size_t)(bb2 * Ss + q + 8)) * Ee + hh * 64 + d;
        *(float2*)(Out + off0) = make_float2(o[j][0] * i0, o[j][1] * i0);
        *(float2*)(Out + off1) = make_float2(o[j][2] * i1, o[j][3] * i1);
    }
}

// ---------------------------------------------------------------------------
extern "C" void kernel_launch(void* const* d_in, const int* in_sizes, int n_in,
                              void* d_out, int out_size)
{
    const float* x  = (const float*)d_in[0];
    const float* Wq = (const float*)d_in[1];
    const float* Wk = (const float*)d_in[2];
    const float* Wv = (const float*)d_in[3];
    float* out = (float*)d_out;

    static bool attr_done = false;
    if (!attr_done) {
        cudaFuncSetAttribute(proj_tc, cudaFuncAttributeMaxDynamicSharedMemorySize,
                             PROJ_SMEM);
        cudaFuncSetAttribute(attn_tc, cudaFuncAttributeMaxDynamicSharedMemorySize,
                             ATTN_SMEM);
        attr_done = true;
    }

    split_xw<<<2048, 256>>>(x, Wq, Wk, Wv);

    dim3 pgrid(Ee / 128, (Bn * Ss) / 128, 3);   // (8, 64, 3)
    proj_tc<<<pgrid, 256, PROJ_SMEM>>>();

    dim3 agrid(Ss / 64, Bn * Hh);               // (32, 64)
    attn_tc<<<agrid, 128, ATTN_SMEM>>>(out);
}